// round 9
// baseline (speedup 1.0000x reference)
#include <cuda_runtime.h>

#define N_PTS   8192
#define C_DIM   64
#define C4      (C_DIM/4)
#define NQ      (3*N_PTS)                 // 24576 queries
#define VOFF    ((size_t)4*N_PTS*C_DIM)   // float offset of out_coords

#define TPB     256
#define NSEG    9
#define SEGSZ   912                       // segs 0..7 = 912 pts, seg 8 = 896
#define QCTA    (NQ/TPB)                  // 96 CTAs per segment
#define GRID1   (NSEG*QCTA)               // 864 CTAs; 864 <= 148*6 => one wave
#define SMEM1   (3*SEGSZ*4)               // 10944 B dynamic smem

#define RPB     29                        // gather rows per CTA (864*29>=NQ)
#define VCP     152                       // value float4s per CTA (864*152>=131072)
#define CCP     10                        // coord points per CTA  (864*10>=8192)

typedef unsigned long long u64;
typedef unsigned int       u32;

// Per-(segment,query) packed partial: (ordered_d_bits << 32) | index.
__device__ u64 g_part[NSEG * NQ];
// Grid-barrier counters (zero-initialized at load; reset each launch below).
__device__ volatile int g_arrive;
__device__ int          g_depart;

// ---------------- packed f32x2 helpers (IEEE RN per lane) -------------------
__device__ __forceinline__ u64 pk2(float lo, float hi) {
    u64 r; asm("mov.b64 %0,{%1,%2};" : "=l"(r) : "f"(lo), "f"(hi)); return r;
}
__device__ __forceinline__ void upk2(float& lo, float& hi, u64 v) {
    asm("mov.b64 {%0,%1},%2;" : "=f"(lo), "=f"(hi) : "l"(v));
}
__device__ __forceinline__ u64 mul2(u64 a, u64 b) {
    u64 r; asm("mul.rn.f32x2 %0,%1,%2;" : "=l"(r) : "l"(a), "l"(b)); return r;
}
__device__ __forceinline__ u64 add2(u64 a, u64 b) {
    u64 r; asm("add.rn.f32x2 %0,%1,%2;" : "=l"(r) : "l"(a), "l"(b)); return r;
}
__device__ __forceinline__ u64 fma2(u64 a, u64 b, u64 c) {
    u64 r; asm("fma.rn.f32x2 %0,%1,%2,%3;" : "=l"(r) : "l"(a), "l"(b), "l"(c)); return r;
}

// d2 for 8 consecutive staged points, bit-exact vs reference:
//   d = RN( RN(sa+sc) - 2m ),  m = fma(a1,c1, RN(a0*c0))
__device__ __forceinline__ void dist8(const float* __restrict__ c0,
                                      const float* __restrict__ c1,
                                      const float* __restrict__ sc,
                                      int j, u64 A0, u64 A1, u64 SA, u64 N2,
                                      float* d)
{
    const ulonglong2 X0 = *reinterpret_cast<const ulonglong2*>(c0 + j);
    const ulonglong2 Y0 = *reinterpret_cast<const ulonglong2*>(c1 + j);
    const ulonglong2 Z0 = *reinterpret_cast<const ulonglong2*>(sc + j);
    const ulonglong2 X1 = *reinterpret_cast<const ulonglong2*>(c0 + j + 4);
    const ulonglong2 Y1 = *reinterpret_cast<const ulonglong2*>(c1 + j + 4);
    const ulonglong2 Z1 = *reinterpret_cast<const ulonglong2*>(sc + j + 4);
    u64 d01 = fma2(fma2(A1, Y0.x, mul2(A0, X0.x)), N2, add2(SA, Z0.x));
    u64 d23 = fma2(fma2(A1, Y0.y, mul2(A0, X0.y)), N2, add2(SA, Z0.y));
    u64 d45 = fma2(fma2(A1, Y1.x, mul2(A0, X1.x)), N2, add2(SA, Z1.x));
    u64 d67 = fma2(fma2(A1, Y1.y, mul2(A0, X1.y)), N2, add2(SA, Z1.y));
    upk2(d[0], d[1], d01);
    upk2(d[2], d[3], d23);
    upk2(d[4], d[5], d45);
    upk2(d[6], d[7], d67);
}

extern __shared__ float smem_dyn[];

// ---------------------------------------------------------------------------
// Single fused persistent kernel:
//   phase 1: segmented argmin -> packed partial (plain store, no atomics)
//   phase 2: arrive at grid barrier, then do copy work while others finish
//   phase 3: spin until all arrived (all 864 CTAs co-resident by construction)
//   phase 4: 9-way partial reduce + value-row gather for this CTA's rows
// Counter reset protocol keeps the kernel replay-deterministic.
// ---------------------------------------------------------------------------
__global__ void __launch_bounds__(TPB, 6)
fused_kernel(const float2* __restrict__ c2,
             const float*  __restrict__ spacing,
             const float*  __restrict__ shift,
             const float4* __restrict__ val4,
             float*        __restrict__ out)
{
    float* c0 = smem_dyn;
    float* c1 = c0 + SEGSZ;
    float* sc = c1 + SEGSZ;

    const int seg  = blockIdx.x / QCTA;
    const int sbeg = seg * SEGSZ;
    const int slen = (seg == NSEG - 1) ? (N_PTS - sbeg) : SEGSZ;

    // ---- stage coords + |c|^2 (mul, mul, add order per reference) ----
    for (int i = threadIdx.x; i < slen; i += TPB) {
        float2 c = __ldg(&c2[sbeg + i]);
        c0[i] = c.x;
        c1[i] = c.y;
        sc[i] = __fadd_rn(__fmul_rn(c.x, c.x), __fmul_rn(c.y, c.y));
    }
    __syncthreads();

    const int q = (blockIdx.x % QCTA) * TPB + threadIdx.x;   // 0..24575
    const int g = q >> 13;
    const int i = q & (N_PTS - 1);

    float2 c  = __ldg(&c2[i]);
    float s0  = __ldg(&spacing[0]), s1  = __ldg(&spacing[1]);
    float sh0 = __ldg(&shift[0]),   sh1 = __ldg(&shift[1]);

    float nc0, nc1;
    if (g == 0)      { nc0 = __fadd_rn(c.x, s0); nc1 = __fadd_rn(c.y, s1); }
    else if (g == 1) { nc0 = c.x;                nc1 = __fadd_rn(c.y, s1); }
    else             { nc0 = __fadd_rn(c.x, s0); nc1 = c.y;                }

    float a0 = __fsub_rn(nc0, sh0);
    float a1 = __fsub_rn(nc1, sh1);
    float sa = __fadd_rn(__fmul_rn(a0, a0), __fmul_rn(a1, a1));

    const u64 A0 = pk2(a0, a0);
    const u64 A1 = pk2(a1, a1);
    const u64 SA = pk2(sa, sa);
    const u64 N2 = pk2(-2.0f, -2.0f);

    float bd   = __int_as_float(0x7f800000);   // +inf
    int   bjit = 0;

    #pragma unroll 1
    for (int j = 0; j < slen; j += 8) {
        float d[8];
        dist8(c0, c1, sc, j, A0, A1, SA, N2, d);

        float m01 = fminf(d[0], d[1]);
        float m23 = fminf(d[2], d[3]);
        float m45 = fminf(d[4], d[5]);
        float m67 = fminf(d[6], d[7]);
        float m03 = fminf(m01, m23);
        float m47 = fminf(m45, m67);
        float gd  = fminf(m03, m47);

        bool pw = gd < bd;          // strict '<': earliest iteration on ties
        bd   = fminf(bd, gd);
        bjit = pw ? j : bjit;
    }

    // Epilogue: first slot whose bit-identically recomputed d equals bd.
    {
        float d[8];
        dist8(c0, c1, sc, bjit, A0, A1, SA, N2, d);
        int slot = 7;
        #pragma unroll
        for (int k = 6; k >= 0; k--)
            slot = (d[k] == bd) ? k : slot;

        // Ordered-float transform: strictly monotone -> u64 min is exact
        // (d, idx) lexicographic = jnp.argmin first occurrence.
        u32 ub = __float_as_uint(bd);
        ub = (ub & 0x80000000u) ? ~ub : (ub | 0x80000000u);
        g_part[seg * NQ + q] = ((u64)ub << 32) | (u32)(sbeg + bjit + slot);
    }
    __syncthreads();   // also fences smem reuse below

    // ---- arrive at grid barrier ----
    if (threadIdx.x == 0) {
        __threadfence();                         // partials visible in L2
        atomicAdd((int*)&g_arrive, 1);
    }

    // ---- independent copy work, overlapped with other CTAs finishing ----
    {
        float4* outv4 = reinterpret_cast<float4*>(out);
        int t = threadIdx.x;
        if (t < VCP) {
            int v = blockIdx.x * VCP + t;
            if (v < N_PTS * C4) outv4[v] = __ldg(&val4[v]);
        } else if (t < VCP + CCP) {
            int p = blockIdx.x * CCP + (t - VCP);
            if (p < N_PTS) {
                float2 cc = __ldg(&c2[p]);
                float xs = __fadd_rn(cc.x, s0);
                float ys = __fadd_rn(cc.y, s1);
                float2* outc = reinterpret_cast<float2*>(out + VOFF);
                outc[p]             = cc;
                outc[N_PTS   + p]   = make_float2(xs,   ys);
                outc[2*N_PTS + p]   = make_float2(cc.x, ys);
                outc[3*N_PTS + p]   = make_float2(xs,   cc.y);
            }
        }
    }

    // ---- spin until all CTAs arrived; replay-safe counter reset ----
    if (threadIdx.x == 0) {
        while (g_arrive != GRID1) __nanosleep(64);
        int p = atomicAdd(&g_depart, 1);         // counts CTAs past the spin
        if (p == GRID1 - 1) {                    // last one out resets both
            g_depart = 0;
            __threadfence();
            *(int*)&g_arrive = 0;
        }
    }
    __syncthreads();

    // ---- reduce 9 partials per row + gather winner value rows ----
    int* widx = reinterpret_cast<int*>(smem_dyn);  // reuse staged-coord smem
    const int qbase = blockIdx.x * RPB;

    if (threadIdx.x < RPB) {
        int row = qbase + threadIdx.x;
        if (row < NQ) {
            u64 best = __ldcg(&g_part[row]);
            #pragma unroll
            for (int s = 1; s < NSEG; s++) {
                u64 k = __ldcg(&g_part[s * NQ + row]);
                best = (k < best) ? k : best;
            }
            widx[threadIdx.x] = (int)(u32)(best & 0xFFFFFFFFull);
        }
    }
    __syncthreads();

    float4* outv4 = reinterpret_cast<float4*>(out);
    for (int t = threadIdx.x; t < RPB * C4; t += TPB) {
        int rr  = t >> 4;
        int ccx = t & (C4 - 1);
        int row = qbase + rr;
        if (row < NQ)
            outv4[(size_t)(N_PTS + row) * C4 + ccx] =
                __ldg(&val4[(size_t)widx[rr] * C4 + ccx]);
    }
}

// ---------------------------------------------------------------------------
extern "C" void kernel_launch(void* const* d_in, const int* in_sizes, int n_in,
                              void* d_out, int out_size)
{
    const float2* c2      = (const float2*)d_in[1];
    const float*  spacing = (const float*) d_in[2];
    const float*  shift   = (const float*) d_in[3];
    const float4* val4    = (const float4*)d_in[0];
    float* out = (float*)d_out;

    fused_kernel<<<GRID1, TPB, SMEM1>>>(c2, spacing, shift, val4, out);
}

// round 10
// speedup vs baseline: 1.0413x; 1.0413x over previous
#include <cuda_runtime.h>

#define N_PTS   8192
#define C_DIM   64
#define C4      (C_DIM/4)
#define NQ      (3*N_PTS)                 // 24576 queries
#define VOFF    ((size_t)4*N_PTS*C_DIM)   // float offset of out_coords

#define TPB     256
#define NSEG    15
#define SEGSZ   552                       // segs 0..13 = 552, seg 14 = 464
#define QPCTA   512                       // queries per CTA (2 per thread)
#define QCTA    (NQ/QPCTA)                // 48 CTAs per segment
#define GRID1   (NSEG*QCTA)               // 720 CTAs <= 148*5 => co-resident
#define SMEM1   (3*SEGSZ*4)               // 6624 B dynamic smem

#define RPB     35                        // gather rows per CTA (720*35>=NQ)
#define VCP     183                       // value float4s per CTA
#define CCP     12                        // coord points per CTA

typedef unsigned long long u64;
typedef unsigned int       u32;

// Per-(segment,query) packed partial: (ordered_d_bits << 32) | index.
__device__ u64 g_part[NSEG * NQ];
// Grid-barrier counters (reset each launch; replay-deterministic).
__device__ volatile int g_arrive;
__device__ int          g_depart;

// ---------------- packed f32x2 helpers (IEEE RN per lane) -------------------
__device__ __forceinline__ u64 pk2(float lo, float hi) {
    u64 r; asm("mov.b64 %0,{%1,%2};" : "=l"(r) : "f"(lo), "f"(hi)); return r;
}
__device__ __forceinline__ void upk2(float& lo, float& hi, u64 v) {
    asm("mov.b64 {%0,%1},%2;" : "=f"(lo), "=f"(hi) : "l"(v));
}
__device__ __forceinline__ u64 mul2(u64 a, u64 b) {
    u64 r; asm("mul.rn.f32x2 %0,%1,%2;" : "=l"(r) : "l"(a), "l"(b)); return r;
}
__device__ __forceinline__ u64 add2(u64 a, u64 b) {
    u64 r; asm("add.rn.f32x2 %0,%1,%2;" : "=l"(r) : "l"(a), "l"(b)); return r;
}
__device__ __forceinline__ u64 fma2(u64 a, u64 b, u64 c) {
    u64 r; asm("fma.rn.f32x2 %0,%1,%2,%3;" : "=l"(r) : "l"(a), "l"(b), "l"(c)); return r;
}

// Query-constant bundle.
struct Q {
    u64 A0, A1, SA;      // packed (a0,a0), (a1,a1), (sa,sa)
    float bd;            // best distance
    int   bj;            // best iteration offset
};

// Exact per-pair semantics: d = RN( RN(sa+sc) - 2m ), m = fma(a1,y,RN(a0*x)).
__device__ __forceinline__ void dist4(u64 Xx, u64 Xy, u64 Yx, u64 Yy,
                                      u64 Zx, u64 Zy, const Q& qq, u64 N2,
                                      float* d)
{
    u64 d01 = fma2(fma2(qq.A1, Yx, mul2(qq.A0, Xx)), N2, add2(qq.SA, Zx));
    u64 d23 = fma2(fma2(qq.A1, Yy, mul2(qq.A0, Xy)), N2, add2(qq.SA, Zy));
    upk2(d[0], d[1], d01);
    upk2(d[2], d[3], d23);
}

__device__ __forceinline__ Q make_query(int q, float2 c, float s0, float s1,
                                        float sh0, float sh1)
{
    int g = q >> 13;
    float nc0, nc1;
    if (g == 0)      { nc0 = __fadd_rn(c.x, s0); nc1 = __fadd_rn(c.y, s1); }
    else if (g == 1) { nc0 = c.x;                nc1 = __fadd_rn(c.y, s1); }
    else             { nc0 = __fadd_rn(c.x, s0); nc1 = c.y;                }
    float a0 = __fsub_rn(nc0, sh0);
    float a1 = __fsub_rn(nc1, sh1);
    float sa = __fadd_rn(__fmul_rn(a0, a0), __fmul_rn(a1, a1));
    Q qq;
    qq.A0 = pk2(a0, a0);
    qq.A1 = pk2(a1, a1);
    qq.SA = pk2(sa, sa);
    qq.bd = __int_as_float(0x7f800000);
    qq.bj = 0;
    return qq;
}

// Epilogue: first slot in winning iteration whose bit-identically recomputed
// distance equals bd; pack ordered (d, idx) key.
__device__ __forceinline__ u64 finish_query(const float* c0, const float* c1,
                                            const float* sc, const Q& qq,
                                            u64 N2, int sbeg)
{
    int j = qq.bj;
    const ulonglong2 X = *reinterpret_cast<const ulonglong2*>(c0 + j);
    const ulonglong2 Y = *reinterpret_cast<const ulonglong2*>(c1 + j);
    const ulonglong2 Z = *reinterpret_cast<const ulonglong2*>(sc + j);
    float d[4];
    dist4(X.x, X.y, Y.x, Y.y, Z.x, Z.y, qq, N2, d);
    int slot = 3;
    slot = (d[2] == qq.bd) ? 2 : slot;
    slot = (d[1] == qq.bd) ? 1 : slot;
    slot = (d[0] == qq.bd) ? 0 : slot;
    u32 ub = __float_as_uint(qq.bd);
    ub = (ub & 0x80000000u) ? ~ub : (ub | 0x80000000u);
    return ((u64)ub << 32) | (u32)(sbeg + j + slot);
}

extern __shared__ float smem_dyn[];

// ---------------------------------------------------------------------------
// Fused persistent kernel, 2 queries per thread (halves smem-crossbar load):
//   phase 1: segmented argmin -> packed partials (plain stores)
//   phase 2: arrive at grid barrier, then overlapped copy work
//   phase 3: spin (all 720 CTAs co-resident by construction)
//   phase 4: NSEG-way partial reduce + value-row gather
// ---------------------------------------------------------------------------
__global__ void __launch_bounds__(TPB, 5)
fused_kernel(const float2* __restrict__ c2,
             const float*  __restrict__ spacing,
             const float*  __restrict__ shift,
             const float4* __restrict__ val4,
             float*        __restrict__ out)
{
    float* c0 = smem_dyn;
    float* c1 = c0 + SEGSZ;
    float* sc = c1 + SEGSZ;

    const int seg  = blockIdx.x / QCTA;
    const int sbeg = seg * SEGSZ;
    const int slen = (seg == NSEG - 1) ? (N_PTS - sbeg) : SEGSZ;

    // ---- stage coords + |c|^2 (mul, mul, add order per reference) ----
    for (int i = threadIdx.x; i < slen; i += TPB) {
        float2 c = __ldg(&c2[sbeg + i]);
        c0[i] = c.x;
        c1[i] = c.y;
        sc[i] = __fadd_rn(__fmul_rn(c.x, c.x), __fmul_rn(c.y, c.y));
    }
    __syncthreads();

    const int qA = (blockIdx.x % QCTA) * QPCTA + threadIdx.x;
    const int qB = qA + TPB;

    float s0  = __ldg(&spacing[0]), s1  = __ldg(&spacing[1]);
    float sh0 = __ldg(&shift[0]),   sh1 = __ldg(&shift[1]);
    const u64 N2 = pk2(-2.0f, -2.0f);

    Q a = make_query(qA, __ldg(&c2[qA & (N_PTS - 1)]), s0, s1, sh0, sh1);
    Q b = make_query(qB, __ldg(&c2[qB & (N_PTS - 1)]), s0, s1, sh0, sh1);

    #pragma unroll 1
    for (int j = 0; j < slen; j += 4) {
        const ulonglong2 X = *reinterpret_cast<const ulonglong2*>(c0 + j);
        const ulonglong2 Y = *reinterpret_cast<const ulonglong2*>(c1 + j);
        const ulonglong2 Z = *reinterpret_cast<const ulonglong2*>(sc + j);

        float dA[4], dB[4];
        dist4(X.x, X.y, Y.x, Y.y, Z.x, Z.y, a, N2, dA);
        dist4(X.x, X.y, Y.x, Y.y, Z.x, Z.y, b, N2, dB);

        float gA = fminf(fminf(dA[0], dA[1]), fminf(dA[2], dA[3]));
        float gB = fminf(fminf(dB[0], dB[1]), fminf(dB[2], dB[3]));

        bool pA = gA < a.bd;                   // strict '<': earliest iter
        a.bd = fminf(a.bd, gA);
        a.bj = pA ? j : a.bj;
        bool pB = gB < b.bd;
        b.bd = fminf(b.bd, gB);
        b.bj = pB ? j : b.bj;
    }

    g_part[seg * NQ + qA] = finish_query(c0, c1, sc, a, N2, sbeg);
    g_part[seg * NQ + qB] = finish_query(c0, c1, sc, b, N2, sbeg);
    __syncthreads();   // also fences smem reuse below

    // ---- arrive at grid barrier ----
    if (threadIdx.x == 0) {
        __threadfence();                       // partials visible in L2
        atomicAdd((int*)&g_arrive, 1);
    }

    // ---- independent copy work, overlapped with other CTAs finishing ----
    {
        float4* outv4 = reinterpret_cast<float4*>(out);
        int t = threadIdx.x;
        if (t < VCP) {
            int v = blockIdx.x * VCP + t;
            if (v < N_PTS * C4) outv4[v] = __ldg(&val4[v]);
        } else if (t < VCP + CCP) {
            int p = blockIdx.x * CCP + (t - VCP);
            if (p < N_PTS) {
                float2 cc = __ldg(&c2[p]);
                float xs = __fadd_rn(cc.x, s0);
                float ys = __fadd_rn(cc.y, s1);
                float2* outc = reinterpret_cast<float2*>(out + VOFF);
                outc[p]             = cc;
                outc[N_PTS   + p]   = make_float2(xs,   ys);
                outc[2*N_PTS + p]   = make_float2(cc.x, ys);
                outc[3*N_PTS + p]   = make_float2(xs,   cc.y);
            }
        }
    }

    // ---- spin until all CTAs arrived; replay-safe counter reset ----
    if (threadIdx.x == 0) {
        while (g_arrive != GRID1) __nanosleep(64);
        int p = atomicAdd(&g_depart, 1);
        if (p == GRID1 - 1) {                  // last one out resets both
            g_depart = 0;
            __threadfence();
            *(int*)&g_arrive = 0;
        }
    }
    __syncthreads();

    // ---- reduce NSEG partials per row + gather winner value rows ----
    int* widx = reinterpret_cast<int*>(smem_dyn);   // reuse staged smem
    const int qbase = blockIdx.x * RPB;

    if (threadIdx.x < RPB) {
        int row = qbase + threadIdx.x;
        if (row < NQ) {
            u64 best = __ldcg(&g_part[row]);
            #pragma unroll
            for (int s = 1; s < NSEG; s++) {
                u64 k = __ldcg(&g_part[s * NQ + row]);
                best = (k < best) ? k : best;
            }
            widx[threadIdx.x] = (int)(u32)(best & 0xFFFFFFFFull);
        }
    }
    __syncthreads();

    float4* outv4 = reinterpret_cast<float4*>(out);
    for (int t = threadIdx.x; t < RPB * C4; t += TPB) {
        int rr  = t >> 4;
        int ccx = t & (C4 - 1);
        int row = qbase + rr;
        if (row < NQ)
            outv4[(size_t)(N_PTS + row) * C4 + ccx] =
                __ldg(&val4[(size_t)widx[rr] * C4 + ccx]);
    }
}

// ---------------------------------------------------------------------------
extern "C" void kernel_launch(void* const* d_in, const int* in_sizes, int n_in,
                              void* d_out, int out_size)
{
    const float4* val4    = (const float4*)d_in[0];
    const float2* c2      = (const float2*)d_in[1];
    const float*  spacing = (const float*) d_in[2];
    const float*  shift   = (const float*) d_in[3];
    float* out = (float*)d_out;

    fused_kernel<<<GRID1, TPB, SMEM1>>>(c2, spacing, shift, val4, out);
}